// round 2
// baseline (speedup 1.0000x reference)
#include <cuda_runtime.h>

// ---------------- sizes ----------------
#define BATCH 256
#define NY 3686400              // 256*64*15*15
#define NY4 921600              // NY/4
#define H1N (256*64*62*62)      // 62,980,096
#define H2N (256*64*31*31)      // 15,745,024

#define ODE_SIN_FLOATS (64*289)         // 18496  (64 x 17 x 17)
#define ODE_SW_FLOATS  (8*9*64)         // 4608
#define ODE_SMEM_BYTES ((ODE_SIN_FLOATS + ODE_SW_FLOATS) * 4)   // 92416

// ---------------- scratch (device globals, no allocation) ----------------
__device__ float g_h1[H1N];
__device__ float g_h2[H2N];
__device__ float g_y[NY];
__device__ float g_ytmp[NY];
__device__ float g_t0[NY];
__device__ float g_t1[NY];
__device__ float g_t2[NY];
__device__ float g_k[6][NY];
__device__ float g_S1[64 * 225];
__device__ float g_S2[64 * 225];
__device__ float g_pool[256 * 64];

// ---------------- helpers ----------------
__inline__ __device__ float warpSum(float v) {
#pragma unroll
    for (int o = 16; o; o >>= 1) v += __shfl_xor_sync(0xffffffffu, v, o);
    return v;
}

// ---------------- conv1: 1->64, 3x3, valid, 64 -> 62 ----------------
// grid (16 tiles, B), block (16,16)
__global__ void conv1_kernel(const float* __restrict__ x, float* __restrict__ out,
                             const float* __restrict__ w, const float* __restrict__ bias)
{
    __shared__ float sx[18][18];
    __shared__ float swt[64 * 9];
    __shared__ float sb[64];
    int b = blockIdx.y;
    int tileX = blockIdx.x & 3, tileY = blockIdx.x >> 2;
    int tx = threadIdx.x, ty = threadIdx.y;
    int tid = ty * 16 + tx;

    for (int s = tid; s < 576; s += 256) swt[s] = w[s];
    if (tid < 64) sb[tid] = bias[tid];

    const float* xb = x + (size_t)b * 64 * 64;
    int ox0 = tileX * 16, oy0 = tileY * 16;
    for (int s = tid; s < 18 * 18; s += 256) {
        int r = s / 18, c = s % 18;
        int iy = oy0 + r, ix = ox0 + c;
        sx[r][c] = (iy < 64 && ix < 64) ? xb[iy * 64 + ix] : 0.f;
    }
    __syncthreads();

    int ox = ox0 + tx, oy = oy0 + ty;
    if (ox >= 62 || oy >= 62) return;

    float v[9];
#pragma unroll
    for (int ky = 0; ky < 3; ky++)
#pragma unroll
        for (int kx = 0; kx < 3; kx++)
            v[ky * 3 + kx] = sx[ty + ky][tx + kx];

    float* ob = out + (size_t)b * 64 * 3844 + oy * 62 + ox;
#pragma unroll 4
    for (int co = 0; co < 64; co++) {
        float a = sb[co];
#pragma unroll
        for (int k = 0; k < 9; k++) a = fmaf(swt[co * 9 + k], v[k], a);
        ob[(size_t)co * 3844] = a;
    }
}

// ---------------- generic GroupNorm (big HW), block 256, grid B*32 ----------------
__global__ void gn_big_kernel(const float* __restrict__ in, float* __restrict__ out,
                              const float* __restrict__ gamma, const float* __restrict__ beta,
                              int HW, int relu)
{
    __shared__ float rs[8], rs2[8], stats[2];
    int bg = blockIdx.x;
    int c0 = (bg & 31) * 2;
    size_t base = (size_t)bg * 2 * HW;
    int n = 2 * HW;
    float s = 0.f, s2 = 0.f;
    for (int i = threadIdx.x; i < n; i += 256) {
        float v = in[base + i];
        s += v; s2 = fmaf(v, v, s2);
    }
    s = warpSum(s); s2 = warpSum(s2);
    int wi = threadIdx.x >> 5, lane = threadIdx.x & 31;
    if (lane == 0) { rs[wi] = s; rs2[wi] = s2; }
    __syncthreads();
    if (threadIdx.x == 0) {
        float a = 0.f, bb = 0.f;
#pragma unroll
        for (int i = 0; i < 8; i++) { a += rs[i]; bb += rs2[i]; }
        float mu = a / (float)n;
        stats[0] = mu;
        stats[1] = rsqrtf(bb / (float)n - mu * mu + 1e-5f);
    }
    __syncthreads();
    float mu = stats[0], inv = stats[1];
    float sc0 = inv * gamma[c0],     sh0 = beta[c0]     - mu * sc0;
    float sc1 = inv * gamma[c0 + 1], sh1 = beta[c0 + 1] - mu * sc1;
    for (int i = threadIdx.x; i < n; i += 256) {
        float v = in[base + i];
        float r = (i < HW) ? fmaf(v, sc0, sh0) : fmaf(v, sc1, sh1);
        if (relu) r = fmaxf(r, 0.f);
        out[base + i] = r;
    }
}

// ---------------- GroupNorm for 15x15 (group span = 450), 1 warp per (b,g) ----------------
// grid B*32, block 32
__global__ void gn225_kernel(const float* __restrict__ in, float* __restrict__ out,
                             const float* __restrict__ gamma, const float* __restrict__ beta,
                             int relu)
{
    int bg = blockIdx.x;
    int lane = threadIdx.x;
    size_t base = (size_t)bg * 450;
    int c0 = (bg & 31) * 2;
    float v[15];
    float s = 0.f, s2 = 0.f;
#pragma unroll
    for (int k = 0; k < 15; k++) {
        int i = k * 32 + lane;
        float xv = (i < 450) ? in[base + i] : 0.f;
        v[k] = xv;
        s += xv; s2 = fmaf(xv, xv, s2);
    }
    s = warpSum(s); s2 = warpSum(s2);
    float mu = s * (1.f / 450.f);
    float inv = rsqrtf(s2 * (1.f / 450.f) - mu * mu + 1e-5f);
    float sc0 = inv * gamma[c0],     sh0 = beta[c0]     - mu * sc0;
    float sc1 = inv * gamma[c0 + 1], sh1 = beta[c0 + 1] - mu * sc1;
#pragma unroll
    for (int k = 0; k < 15; k++) {
        int i = k * 32 + lane;
        if (i < 450) {
            float r = (i < 225) ? fmaf(v[k], sc0, sh0) : fmaf(v[k], sc1, sh1);
            if (relu) r = fmaxf(r, 0.f);
            out[base + i] = r;
        }
    }
}

// ---------------- conv 4x4 stride 2 pad 1 (64->64), square ----------------
// grid (pixTiles, 16, B), block 256 ; each thread: 4 co x 1 pixel
__global__ void conv4x4_kernel(const float* __restrict__ in, float* __restrict__ out,
                               const float* __restrict__ w, const float* __restrict__ bias,
                               int Hin, int Hout)
{
    __shared__ float sw[4 * 64 * 16];
    int b = blockIdx.z;
    int co0 = blockIdx.y * 4;
    int tid = threadIdx.x;
    for (int s = tid; s < 4096; s += 256) {
        int j = s >> 10;
        int ci = (s >> 4) & 63;
        int tp = s & 15;
        sw[s] = w[(((size_t)(co0 + j)) * 64 + ci) * 16 + tp];
    }
    __syncthreads();

    int p = blockIdx.x * 256 + tid;
    int HW = Hout * Hout;
    if (p >= HW) return;
    int oy = p / Hout, ox = p % Hout;

    float a0 = bias[co0], a1 = bias[co0 + 1], a2 = bias[co0 + 2], a3 = bias[co0 + 3];
    const float* inb = in + (size_t)b * 64 * Hin * Hin;

    for (int ci = 0; ci < 64; ci++) {
        const float* inc = inb + (size_t)ci * Hin * Hin;
        const float* sw0 = sw + ci * 16;
        const float* sw1 = sw + 1024 + ci * 16;
        const float* sw2 = sw + 2048 + ci * 16;
        const float* sw3 = sw + 3072 + ci * 16;
#pragma unroll
        for (int ky = 0; ky < 4; ky++) {
            int iy = oy * 2 - 1 + ky;
            if ((unsigned)iy < (unsigned)Hin) {
#pragma unroll
                for (int kx = 0; kx < 4; kx++) {
                    int ix = ox * 2 - 1 + kx;
                    if ((unsigned)ix < (unsigned)Hin) {
                        float v = __ldg(inc + iy * Hin + ix);
                        int tp = ky * 4 + kx;
                        a0 = fmaf(v, sw0[tp], a0);
                        a1 = fmaf(v, sw1[tp], a1);
                        a2 = fmaf(v, sw2[tp], a2);
                        a3 = fmaf(v, sw3[tp], a3);
                    }
                }
            }
        }
    }
    size_t ob = (((size_t)b * 64 + co0) * HW) + p;
    out[ob] = a0; out[ob + HW] = a1; out[ob + 2 * (size_t)HW] = a2; out[ob + 3 * (size_t)HW] = a3;
}

// ---------------- precompute S[co][p] = sum of valid channel-0 taps ----------------
// grid 64, block 225
__global__ void precomp_s_kernel(const float* __restrict__ w, float* __restrict__ S)
{
    int co = blockIdx.x;
    int p = threadIdx.x;
    int y = p / 15, x = p % 15;
    float a = 0.f;
#pragma unroll
    for (int ky = 0; ky < 3; ky++) {
        int iy = y - 1 + ky;
        if ((unsigned)iy < 15u) {
#pragma unroll
            for (int kx = 0; kx < 3; kx++) {
                int ix = x - 1 + kx;
                if ((unsigned)ix < 15u) a += w[(size_t)co * 65 * 9 + ky * 3 + kx];
            }
        }
    }
    S[co * 225 + p] = a;
}

// ---------------- ODE conv: 64->64, 3x3 pad1 on 15x15, + bias + t*S ----------------
// grid B, block 256, dyn smem 92416B. thread: 4 co x up-to-15 pixels
__global__ void __launch_bounds__(256, 2)
ode_conv_kernel(const float* __restrict__ in, float* __restrict__ out,
                const float* __restrict__ w,      // [64][65][3][3]
                const float* __restrict__ bias,   // [64]
                const float* __restrict__ S,      // [64][225]
                float t)
{
    extern __shared__ float smem[];
    float* sin_ = smem;                  // 64 x 17 x 17 zero-halo
    float* sw   = smem + ODE_SIN_FLOATS; // 8ci x 9 x 64co

    int b = blockIdx.x;
    int tid = threadIdx.x;

    for (int i = tid; i < ODE_SIN_FLOATS; i += 256) sin_[i] = 0.f;
    __syncthreads();
    const float* inb = in + (size_t)b * 64 * 225;
    for (int i = tid; i < 64 * 225; i += 256) {
        int ci = i / 225, p = i % 225;
        int y = p / 15, x = p % 15;
        sin_[ci * 289 + (y + 1) * 17 + (x + 1)] = inb[i];
    }

    int cg = tid >> 4;          // 0..15 -> co0 = 4*cg
    int pg = tid & 15;          // pixel phase
    int co0 = cg * 4;

    int offs[15];
#pragma unroll
    for (int j = 0; j < 15; j++) {
        int p = 16 * j + pg;
        if (p >= 225) p = 0;    // dummy (result discarded)
        offs[j] = (p / 15) * 17 + (p % 15);
    }

    float acc[4][15];
#pragma unroll
    for (int a = 0; a < 4; a++)
#pragma unroll
        for (int j = 0; j < 15; j++) acc[a][j] = 0.f;

    for (int cc = 0; cc < 8; cc++) {
        __syncthreads();   // also covers initial sin_ fill on cc==0
        for (int s = tid; s < ODE_SW_FLOATS; s += 256) {
            int co = s & 63;
            int r = s >> 6;
            int k9 = r % 9;
            int ciL = r / 9;
            sw[s] = w[((size_t)co * 65 + (cc * 8 + ciL + 1)) * 9 + k9];
        }
        __syncthreads();

        for (int ciL = 0; ciL < 8; ciL++) {
            int sbase = (cc * 8 + ciL) * 289;
#pragma unroll
            for (int k9 = 0; k9 < 9; k9++) {
                int ky = k9 / 3, kx = k9 % 3;
                const float4 wv = *reinterpret_cast<const float4*>(&sw[(ciL * 9 + k9) * 64 + co0]);
                int tb = sbase + ky * 17 + kx;
#pragma unroll
                for (int j = 0; j < 15; j++) {
                    float v = sin_[tb + offs[j]];
                    acc[0][j] = fmaf(wv.x, v, acc[0][j]);
                    acc[1][j] = fmaf(wv.y, v, acc[1][j]);
                    acc[2][j] = fmaf(wv.z, v, acc[2][j]);
                    acc[3][j] = fmaf(wv.w, v, acc[3][j]);
                }
            }
        }
    }

    float* outb = out + (size_t)b * 64 * 225;
    float bv[4];
#pragma unroll
    for (int a = 0; a < 4; a++) bv[a] = bias[co0 + a];
#pragma unroll
    for (int j = 0; j < 15; j++) {
        int p = 16 * j + pg;
        if (p < 225) {
#pragma unroll
            for (int a = 0; a < 4; a++) {
                int co = co0 + a;
                outb[co * 225 + p] = acc[a][j] + bv[a] + t * __ldg(&S[co * 225 + p]);
            }
        }
    }
}

// ---------------- dopri combine: dst = y + sum_j c_j * k_j  (float4) ----------------
// grid 3600, block 256 (exact NY4)
__global__ void combine_kernel(const float4* __restrict__ y, float4* __restrict__ dst,
                               const float4* __restrict__ p0, const float4* __restrict__ p1,
                               const float4* __restrict__ p2, const float4* __restrict__ p3,
                               const float4* __restrict__ p4,
                               float c0, float c1, float c2, float c3, float c4, int n)
{
    int i = blockIdx.x * 256 + threadIdx.x;
    float4 a = y[i];
    float4 t = p0[i];
    a.x = fmaf(c0, t.x, a.x); a.y = fmaf(c0, t.y, a.y); a.z = fmaf(c0, t.z, a.z); a.w = fmaf(c0, t.w, a.w);
    if (n > 1) { t = p1[i]; a.x = fmaf(c1, t.x, a.x); a.y = fmaf(c1, t.y, a.y); a.z = fmaf(c1, t.z, a.z); a.w = fmaf(c1, t.w, a.w); }
    if (n > 2) { t = p2[i]; a.x = fmaf(c2, t.x, a.x); a.y = fmaf(c2, t.y, a.y); a.z = fmaf(c2, t.z, a.z); a.w = fmaf(c2, t.w, a.w); }
    if (n > 3) { t = p3[i]; a.x = fmaf(c3, t.x, a.x); a.y = fmaf(c3, t.y, a.y); a.z = fmaf(c3, t.z, a.z); a.w = fmaf(c3, t.w, a.w); }
    if (n > 4) { t = p4[i]; a.x = fmaf(c4, t.x, a.x); a.y = fmaf(c4, t.y, a.y); a.z = fmaf(c4, t.z, a.z); a.w = fmaf(c4, t.w, a.w); }
    dst[i] = a;
}

// ---------------- global mean pool: one warp per (b,c) over 225 ----------------
// grid 2048, block 256
__global__ void pool_kernel(const float* __restrict__ in, float* __restrict__ out)
{
    int gw = (blockIdx.x * 256 + threadIdx.x) >> 5;   // 0..16383
    int lane = threadIdx.x & 31;
    const float* p = in + (size_t)gw * 225;
    float s = 0.f;
    for (int i = lane; i < 225; i += 32) s += p[i];
    s = warpSum(s);
    if (lane == 0) out[gw] = s * (1.f / 225.f);
}

// ---------------- FC 64->10 ----------------
// grid 256, block 64
__global__ void fc_kernel(const float* __restrict__ pool, const float* __restrict__ w,
                          const float* __restrict__ bias, float* __restrict__ out)
{
    __shared__ float sp[64];
    int b = blockIdx.x;
    sp[threadIdx.x] = pool[b * 64 + threadIdx.x];
    __syncthreads();
    if (threadIdx.x < 10) {
        float a = bias[threadIdx.x];
#pragma unroll
        for (int c = 0; c < 64; c++) a = fmaf(sp[c], __ldg(&w[threadIdx.x * 64 + c]), a);
        out[b * 10 + threadIdx.x] = a;
    }
}

// ---------------- launch ----------------
extern "C" void kernel_launch(void* const* d_in, const int* in_sizes, int n_in,
                              void* d_out, int out_size)
{
    const float* x        = (const float*)d_in[0];
    const float* conv1_w  = (const float*)d_in[1];
    const float* conv1_b  = (const float*)d_in[2];
    const float* gn1_g    = (const float*)d_in[3];
    const float* gn1_b    = (const float*)d_in[4];
    const float* conv2_w  = (const float*)d_in[5];
    const float* conv2_b  = (const float*)d_in[6];
    const float* gn2_g    = (const float*)d_in[7];
    const float* gn2_b    = (const float*)d_in[8];
    const float* conv3_w  = (const float*)d_in[9];
    const float* conv3_b  = (const float*)d_in[10];
    const float* f_gn1_g  = (const float*)d_in[11];
    const float* f_gn1_b  = (const float*)d_in[12];
    const float* f_conv1_w= (const float*)d_in[13];
    const float* f_conv1_b= (const float*)d_in[14];
    const float* f_gn2_g  = (const float*)d_in[15];
    const float* f_gn2_b  = (const float*)d_in[16];
    const float* f_conv2_w= (const float*)d_in[17];
    const float* f_conv2_b= (const float*)d_in[18];
    const float* f_gn3_g  = (const float*)d_in[19];
    const float* f_gn3_b  = (const float*)d_in[20];
    const float* out_gn_g = (const float*)d_in[21];
    const float* out_gn_b = (const float*)d_in[22];
    const float* fc_w     = (const float*)d_in[23];
    const float* fc_b     = (const float*)d_in[24];
    float* out = (float*)d_out;

    float *h1, *h2, *y, *ytmp, *t0b, *t1b, *t2b, *kbase, *S1, *S2, *pool;
    cudaGetSymbolAddress((void**)&h1, g_h1);
    cudaGetSymbolAddress((void**)&h2, g_h2);
    cudaGetSymbolAddress((void**)&y, g_y);
    cudaGetSymbolAddress((void**)&ytmp, g_ytmp);
    cudaGetSymbolAddress((void**)&t0b, g_t0);
    cudaGetSymbolAddress((void**)&t1b, g_t1);
    cudaGetSymbolAddress((void**)&t2b, g_t2);
    cudaGetSymbolAddress((void**)&kbase, g_k);
    cudaGetSymbolAddress((void**)&S1, g_S1);
    cudaGetSymbolAddress((void**)&S2, g_S2);
    cudaGetSymbolAddress((void**)&pool, g_pool);
    float* kk[6];
    for (int i = 0; i < 6; i++) kk[i] = kbase + (size_t)i * NY;

    cudaFuncSetAttribute(ode_conv_kernel, cudaFuncAttributeMaxDynamicSharedMemorySize, ODE_SMEM_BYTES);

    // ---- downsampling ----
    conv1_kernel<<<dim3(16, BATCH), dim3(16, 16)>>>(x, h1, conv1_w, conv1_b);
    gn_big_kernel<<<BATCH * 32, 256>>>(h1, h1, gn1_g, gn1_b, 62 * 62, 1);
    conv4x4_kernel<<<dim3(4, 16, BATCH), 256>>>(h1, h2, conv2_w, conv2_b, 62, 31);
    gn_big_kernel<<<BATCH * 32, 256>>>(h2, h2, gn2_g, gn2_b, 31 * 31, 1);
    conv4x4_kernel<<<dim3(1, 16, BATCH), 256>>>(h2, y, conv3_w, conv3_b, 31, 15);

    // ---- t-channel conv contribution maps ----
    precomp_s_kernel<<<64, 225>>>(f_conv1_w, S1);
    precomp_s_kernel<<<64, 225>>>(f_conv2_w, S2);

    auto feval = [&](float t, const float* yin, float* kout) {
        gn225_kernel<<<BATCH * 32, 32>>>(yin, t0b, f_gn1_g, f_gn1_b, 1);
        ode_conv_kernel<<<BATCH, 256, ODE_SMEM_BYTES>>>(t0b, t1b, f_conv1_w, f_conv1_b, S1, t);
        gn225_kernel<<<BATCH * 32, 32>>>(t1b, t1b, f_gn2_g, f_gn2_b, 1);
        ode_conv_kernel<<<BATCH, 256, ODE_SMEM_BYTES>>>(t1b, t2b, f_conv2_w, f_conv2_b, S2, t);
        gn225_kernel<<<BATCH * 32, 32>>>(t2b, kout, f_gn3_g, f_gn3_b, 0);
    };
    auto comb = [&](float* dst, const float* yin,
                    const float* p0, const float* p1, const float* p2,
                    const float* p3, const float* p4,
                    double c0, double c1, double c2, double c3, double c4, int n) {
        combine_kernel<<<3600, 256>>>((const float4*)yin, (float4*)dst,
            (const float4*)p0,
            (const float4*)(p1 ? p1 : p0), (const float4*)(p2 ? p2 : p0),
            (const float4*)(p3 ? p3 : p0), (const float4*)(p4 ? p4 : p0),
            (float)c0, (float)c1, (float)c2, (float)c3, (float)c4, n);
    };

    const double hs = 1.0 / 8.0;
    for (int st = 0; st < 8; st++) {
        double T0 = st * hs;
        feval((float)T0, y, kk[0]);
        comb(ytmp, y, kk[0], 0, 0, 0, 0, hs * (1.0 / 5.0), 0, 0, 0, 0, 1);
        feval((float)(T0 + hs / 5.0), ytmp, kk[1]);
        comb(ytmp, y, kk[0], kk[1], 0, 0, 0, hs * (3.0 / 40.0), hs * (9.0 / 40.0), 0, 0, 0, 2);
        feval((float)(T0 + 0.3 * hs), ytmp, kk[2]);
        comb(ytmp, y, kk[0], kk[1], kk[2], 0, 0,
             hs * (44.0 / 45.0), hs * (-56.0 / 15.0), hs * (32.0 / 9.0), 0, 0, 3);
        feval((float)(T0 + 0.8 * hs), ytmp, kk[3]);
        comb(ytmp, y, kk[0], kk[1], kk[2], kk[3], 0,
             hs * (19372.0 / 6561.0), hs * (-25360.0 / 2187.0),
             hs * (64448.0 / 6561.0), hs * (-212.0 / 729.0), 0, 4);
        feval((float)(T0 + (8.0 / 9.0) * hs), ytmp, kk[4]);
        comb(ytmp, y, kk[0], kk[1], kk[2], kk[3], kk[4],
             hs * (9017.0 / 3168.0), hs * (-355.0 / 33.0), hs * (46732.0 / 5247.0),
             hs * (49.0 / 176.0), hs * (-5103.0 / 18656.0), 5);
        feval((float)(T0 + hs), ytmp, kk[5]);
        comb(y, y, kk[0], kk[2], kk[3], kk[4], kk[5],
             hs * (35.0 / 384.0), hs * (500.0 / 1113.0), hs * (125.0 / 192.0),
             hs * (-2187.0 / 6784.0), hs * (11.0 / 84.0), 5);
    }

    // ---- head ----
    gn225_kernel<<<BATCH * 32, 32>>>(y, t0b, out_gn_g, out_gn_b, 1);
    pool_kernel<<<2048, 256>>>(t0b, pool);
    fc_kernel<<<BATCH, 64>>>(pool, fc_w, fc_b, out);
}